// round 14
// baseline (speedup 1.0000x reference)
#include <cuda_runtime.h>
#include <cuda_fp16.h>
#include <math.h>
#include <stdint.h>

#define Kc 32
#define Dd 128
#define Nn 65536
#define EPSc 1e-6f
#define NCTA (Nn / 128)
#define KSPL 2
#define KPC  (Kc / KSPL)   // components per CTA

// ---------------- device scratch (no allocs allowed) ----------------
__device__ __half g_Ah[Kc * Dd * Dd];   // A = Sigma^{-1/2}, f16, ldmatrix-swizzled
__device__ float  g_b[Kc * Dd];         // b_k = A_k @ mu_k (fp32)
__device__ float  g_tp1[Kc * 4 * 2];
__device__ float  g_tp2[Kc * 4 * 2];
__device__ float  g_pr[(size_t)Kc * NCTA * 2 * 128];  // maha partials (2 halves)

__device__ __forceinline__ uint32_t sw_off(uint32_t row, uint32_t col) {
    return row * 256u + (((col >> 3) ^ (row & 7u)) << 4) + (col & 7u) * 2u;
}
__device__ __forceinline__ uint32_t s2u(const void* p) {
    uint32_t a;
    asm("{ .reg .u64 t; cvta.to.shared.u64 t, %1; cvt.u32.u64 %0, t; }" : "=r"(a) : "l"(p));
    return a;
}
__device__ __forceinline__ void cpasync16(uint32_t dst, const void* src) {
    asm volatile("cp.async.cg.shared.global [%0], [%1], 16;" :: "r"(dst), "l"(src));
}
#define CP_COMMIT() asm volatile("cp.async.commit_group;" ::: "memory")
#define CP_WAIT1()  asm volatile("cp.async.wait_group 1;" ::: "memory")

__device__ __forceinline__ void ldsm4(uint32_t* r, uint32_t a) {
    asm volatile("ldmatrix.sync.aligned.m8n8.x4.shared.b16 {%0,%1,%2,%3}, [%4];"
        : "=r"(r[0]), "=r"(r[1]), "=r"(r[2]), "=r"(r[3]) : "r"(a));
}
__device__ __forceinline__ void ldsm4t(uint32_t* r, uint32_t a) {
    asm volatile("ldmatrix.sync.aligned.m8n8.x4.trans.shared.b16 {%0,%1,%2,%3}, [%4];"
        : "=r"(r[0]), "=r"(r[1]), "=r"(r[2]), "=r"(r[3]) : "r"(a));
}
__device__ __forceinline__ void mma16816(float* d, const uint32_t* a, const uint32_t* b) {
    asm volatile("mma.sync.aligned.m16n8k16.row.col.f32.f16.f16.f32 "
        "{%0,%1,%2,%3}, {%4,%5,%6,%7}, {%8,%9}, {%0,%1,%2,%3};"
        : "+f"(d[0]), "+f"(d[1]), "+f"(d[2]), "+f"(d[3])
        : "r"(a[0]), "r"(a[1]), "r"(a[2]), "r"(a[3]), "r"(b[0]), "r"(b[1]));
}

__device__ __forceinline__ void cta_red2(float& a, float& b, float* aux) {
    #pragma unroll
    for (int o = 16; o > 0; o >>= 1) {
        a += __shfl_xor_sync(0xffffffffu, a, o);
        b += __shfl_xor_sync(0xffffffffu, b, o);
    }
    int w = threadIdx.x >> 5, l = threadIdx.x & 31;
    if (l == 0) { aux[w] = a; aux[8 + w] = b; }
    __syncthreads();
    if (threadIdx.x == 0) {
        a = 0.f; b = 0.f;
        #pragma unroll
        for (int i = 0; i < 8; i++) { a += aux[i]; b += aux[8 + i]; }
    }
}

#define EP 132

// ---------------------------------------------------------------------------
// Fused prep: grid (Kc, 4). E2 slab in regs->smem; E3 slab; A = I + S f16
// swizzled; b = A mu; partial traces.
// ---------------------------------------------------------------------------
__global__ __launch_bounds__(256) void prep12(const float* __restrict__ cov,
                                              const float* __restrict__ mu) {
    extern __shared__ float sh2[];
    float* sE  = sh2;                    // [128][EP]
    float* sE2 = sh2 + Dd * EP;          // [32][EP]
    float* sMu = sE2 + 32 * EP;          // [128]
    __shared__ float aux[16];
    const int k = blockIdx.x, slab = blockIdx.y * 32;
    const int tid = threadIdx.x;
    const float* ck = cov + (size_t)k * Dd * Dd;

    for (int idx = tid; idx < Dd * Dd; idx += 256) {
        int i = idx >> 7, j = idx & 127;
        sE[i * EP + j] = ck[idx] - (i == j ? (1.f - EPSc) : 0.f);
    }
    if (tid < Dd) sMu[tid] = mu[k * Dd + tid];
    __syncthreads();

    float t1 = 0.f, t2 = 0.f;
    for (int idx = tid; idx < 32 * Dd; idx += 256) {
        int i = slab + (idx >> 7), j = idx & 127;
        float e = sE[i * EP + j];
        t2 += e * e;
        if (i == j) t1 += e;
    }

    const int ti = tid >> 5, tj = tid & 31;
    const int r0 = ti * 4, j0 = tj * 4;

    float acc2[4][4];
    #pragma unroll
    for (int a = 0; a < 4; a++)
        #pragma unroll
        for (int b = 0; b < 4; b++) acc2[a][b] = 0.f;
    for (int m = 0; m < Dd; m++) {
        float4 bv = *(const float4*)&sE[m * EP + j0];
        #pragma unroll
        for (int a = 0; a < 4; a++) {
            float av = sE[(slab + r0 + a) * EP + m];
            acc2[a][0] = fmaf(av, bv.x, acc2[a][0]);
            acc2[a][1] = fmaf(av, bv.y, acc2[a][1]);
            acc2[a][2] = fmaf(av, bv.z, acc2[a][2]);
            acc2[a][3] = fmaf(av, bv.w, acc2[a][3]);
        }
    }
    float t3 = 0.f, t4 = 0.f;
    #pragma unroll
    for (int a = 0; a < 4; a++)
        #pragma unroll
        for (int b = 0; b < 4; b++) {
            float e2 = acc2[a][b];
            t3 += e2 * sE[(slab + r0 + a) * EP + j0 + b];
            t4 += e2 * e2;
        }
    #pragma unroll
    for (int a = 0; a < 4; a++)
        *(float4*)&sE2[(r0 + a) * EP + j0] =
            make_float4(acc2[a][0], acc2[a][1], acc2[a][2], acc2[a][3]);
    __syncthreads();

    float acc3[4][4];
    #pragma unroll
    for (int a = 0; a < 4; a++)
        #pragma unroll
        for (int b = 0; b < 4; b++) acc3[a][b] = 0.f;
    for (int m = 0; m < Dd; m++) {
        float4 bv = *(const float4*)&sE[m * EP + j0];
        #pragma unroll
        for (int a = 0; a < 4; a++) {
            float av = sE2[(r0 + a) * EP + m];
            acc3[a][0] = fmaf(av, bv.x, acc3[a][0]);
            acc3[a][1] = fmaf(av, bv.y, acc3[a][1]);
            acc3[a][2] = fmaf(av, bv.z, acc3[a][2]);
            acc3[a][3] = fmaf(av, bv.w, acc3[a][3]);
        }
    }

    __half* Ak = g_Ah + (size_t)k * Dd * Dd;
    float rb[4] = {0.f, 0.f, 0.f, 0.f};
    #pragma unroll
    for (int a = 0; a < 4; a++) {
        int i = slab + r0 + a;
        #pragma unroll
        for (int b = 0; b < 4; b++) {
            int j = j0 + b;
            float e  = sE[i * EP + j];
            float v = ((i == j) ? 1.f : 0.f) - 0.5f * e + 0.375f * acc2[a][b]
                      - 0.3125f * acc3[a][b];
            Ak[sw_off((uint32_t)i, (uint32_t)j) >> 1] = __float2half(v);
            rb[a] = fmaf(v, sMu[j], rb[a]);
        }
    }
    #pragma unroll
    for (int a = 0; a < 4; a++) {
        #pragma unroll
        for (int o = 16; o > 0; o >>= 1)
            rb[a] += __shfl_xor_sync(0xffffffffu, rb[a], o);
        if (tj == 0) g_b[k * Dd + slab + r0 + a] = rb[a];
    }

    cta_red2(t1, t2, aux);
    if (tid == 0) {
        g_tp1[(k * 4 + blockIdx.y) * 2 + 0] = t1;
        g_tp1[(k * 4 + blockIdx.y) * 2 + 1] = t2;
    }
    __syncthreads();
    cta_red2(t3, t4, aux);
    if (tid == 0) {
        g_tp2[(k * 4 + blockIdx.y) * 2 + 0] = t3;
        g_tp2[(k * 4 + blockIdx.y) * 2 + 1] = t4;
    }
}

// ---------------------------------------------------------------------------
// Main: grid (NCTA, KSPL); A staged in pairs; prologue before X convert.
// ---------------------------------------------------------------------------
#define XS_OFF 0
#define A0_OFF 32768           // pair buffer 0: 64KB
#define A1_OFF 98304           // pair buffer 1: 64KB
#define BS_OFF 163840          // KPC*Dd fp32 = 8KB
#define SMEM_MAIN 172032

__device__ __forceinline__ void loadB(uint32_t bbuf[8][2], uint32_t ab, int ks,
                                      int wn, int l) {
    #pragma unroll
    for (int p = 0; p < 4; p++) {
        uint32_t tmp[4];
        int row = wn * 64 + p * 16 + ((l >> 4) << 3) + (l & 7);
        int ch  = ks * 2 + ((l >> 3) & 1);
        ldsm4t(tmp, ab + (uint32_t)(row * 256 + ((ch ^ (row & 7)) << 4)));
        bbuf[p*2][0]   = tmp[0]; bbuf[p*2][1]   = tmp[1];
        bbuf[p*2+1][0] = tmp[2]; bbuf[p*2+1][1] = tmp[3];
    }
}

__global__ void __launch_bounds__(256, 1) gmm_main(const float* __restrict__ x) {
    extern __shared__ char sm[];
    const uint32_t smb = s2u(sm);
    const int tid = threadIdx.x;
    const int wid = tid >> 5, l = tid & 31;
    const int wm = wid & 3, wn = wid >> 2;
    const int n0 = blockIdx.x * 128;
    const int k0 = blockIdx.y * KPC;

    float* bs = (float*)(sm + BS_OFF);

    // Prologue FIRST: pair (k0, k0+1) -> buf0; latency hides behind X convert.
    for (int ch = tid; ch < 4096; ch += 256)
        cpasync16(smb + A0_OFF + ch * 16, (const char*)g_Ah + (size_t)k0 * 32768 + ch * 16);
    CP_COMMIT();

    // X tile -> f16 swizzled SMEM
    for (int ch = tid; ch < 2048; ch += 256) {
        int row = ch >> 4, cc = (ch & 15) * 8;
        const float4* src = (const float4*)(x + (size_t)(n0 + row) * Dd + cc);
        float4 u = src[0], v = src[1];
        __half2 h[4] = { __floats2half2_rn(u.x, u.y), __floats2half2_rn(u.z, u.w),
                         __floats2half2_rn(v.x, v.y), __floats2half2_rn(v.z, v.w) };
        *(uint4*)(sm + XS_OFF + sw_off((uint32_t)row, (uint32_t)cc)) = *(uint4*)h;
    }
    for (int i = tid; i < KPC * Dd; i += 256) bs[i] = g_b[k0 * Dd + i];
    __syncthreads();

    // Preload X fragments: 2 m-tiles x 8 k-steps, register resident.
    uint32_t xa[2][8][4];
    #pragma unroll
    for (int mt = 0; mt < 2; mt++)
        #pragma unroll
        for (int ks = 0; ks < 8; ks++) {
            int row = wm * 32 + mt * 16 + (l & 15);
            int ch  = ks * 2 + (l >> 4);
            ldsm4(xa[mt][ks], smb + XS_OFF + (uint32_t)(row * 256 + ((ch ^ (row & 7)) << 4)));
        }

    // partial-store base: [k][cta][wn][128]
    float* prb = g_pr + ((size_t)blockIdx.x * 2 + wn) * 128 + wm * 32 + (l >> 2);

    for (int kp = 0; kp < KPC; kp += 2) {
        __syncthreads();  // all warps done reading the buffer being overwritten
        {   // prefetch next pair
            int kn = k0 + ((kp + 2) & (KPC - 1));
            const char* src = (const char*)g_Ah + (size_t)kn * 32768;
            uint32_t dst = smb + ((((kp >> 1) + 1) & 1) ? A1_OFF : A0_OFF);
            for (int ch = tid; ch < 4096; ch += 256)
                cpasync16(dst + ch * 16, src + ch * 16);
            CP_COMMIT();
        }
        CP_WAIT1();
        __syncthreads();  // current pair visible

        const uint32_t pb = smb + (((kp >> 1) & 1) ? A1_OFF : A0_OFF);

        #pragma unroll
        for (int s = 0; s < 2; s++) {
            const int kk = kp + s;
            const int k = k0 + kk;
            const uint32_t ab = pb + s * 32768;

            float acc[2][8][4];
            #pragma unroll
            for (int mt = 0; mt < 2; mt++)
                #pragma unroll
                for (int nt = 0; nt < 8; nt++)
                    #pragma unroll
                    for (int e = 0; e < 4; e++) acc[mt][nt][e] = 0.f;

            uint32_t bb[2][8][2];
            loadB(bb[0], ab, 0, wn, l);
            #pragma unroll
            for (int ks = 0; ks < 8; ks++) {
                if (ks < 7) loadB(bb[(ks + 1) & 1], ab, ks + 1, wn, l);
                #pragma unroll
                for (int mt = 0; mt < 2; mt++)
                    #pragma unroll
                    for (int nt = 0; nt < 8; nt++)
                        mma16816(acc[mt][nt], xa[mt][ks], bb[ks & 1][nt]);
            }

            float pr[4] = {0.f, 0.f, 0.f, 0.f};
            #pragma unroll
            for (int nt = 0; nt < 8; nt++) {
                int d0 = wn * 64 + nt * 8 + (l & 3) * 2;
                float b0 = bs[kk * Dd + d0], b1 = bs[kk * Dd + d0 + 1];
                #pragma unroll
                for (int mt = 0; mt < 2; mt++) {
                    float t0 = acc[mt][nt][0] - b0, t1 = acc[mt][nt][1] - b1;
                    pr[mt*2]   = fmaf(t0, t0, fmaf(t1, t1, pr[mt*2]));
                    float t2 = acc[mt][nt][2] - b0, t3 = acc[mt][nt][3] - b1;
                    pr[mt*2+1] = fmaf(t2, t2, fmaf(t3, t3, pr[mt*2+1]));
                }
            }
            #pragma unroll
            for (int q = 0; q < 4; q++) {
                pr[q] += __shfl_xor_sync(0xffffffffu, pr[q], 1);
                pr[q] += __shfl_xor_sync(0xffffffffu, pr[q], 2);
            }
            if ((l & 3) == 0) {
                float* pk = prb + (size_t)k * NCTA * 2 * 128;
                pk[0]  = pr[0];
                pk[8]  = pr[1];
                pk[16] = pr[2];
                pk[24] = pr[3];
            }
        }
    }
}

// ---------------------------------------------------------------------------
// LSE kernel: grid NCTA, block 256 = 128 samples x 2 k-halves. Folds the
// cst computation (ex-prep3) in from the trace partials. Split-k halves the
// per-thread load chain (32 loads, fits registers, full MLP); smem combine.
// ---------------------------------------------------------------------------
__global__ __launch_bounds__(256) void lse_kernel(const float* __restrict__ w,
                                                  float* __restrict__ out) {
    __shared__ float cs[Kc];
    __shared__ float sMx[128], sSs[128];
    const int tid = threadIdx.x;

    if (tid < Kc) {   // fold ex-prep3: cst[k] from trace partials (L2-hot)
        int k = tid;
        float t1 = 0.f, t2 = 0.f, t3 = 0.f, t4 = 0.f;
        #pragma unroll
        for (int s = 0; s < 4; s++) {
            t1 += g_tp1[(k * 4 + s) * 2 + 0];
            t2 += g_tp1[(k * 4 + s) * 2 + 1];
            t3 += g_tp2[(k * 4 + s) * 2 + 0];
            t4 += g_tp2[(k * 4 + s) * 2 + 1];
        }
        float hld = 0.5f * (t1 - 0.5f * t2 + t3 / 3.f - 0.25f * t4);
        cs[k] = -0.5f * (float)Dd * 1.8378770664093453f - hld + logf(w[k]);
    }
    __syncthreads();

    const int h = tid >> 7, nl = tid & 127;
    const float* p = g_pr + (size_t)blockIdx.x * 256 + nl;

    float v[16];
    #pragma unroll
    for (int i = 0; i < 16; i++) {
        const float* pk = p + (size_t)(h * 16 + i) * NCTA * 256;
        v[i] = pk[0] + pk[128];          // independent loads -> front-batched
    }
    #pragma unroll
    for (int i = 0; i < 16; i++)
        v[i] = cs[h * 16 + i] - 0.5f * v[i];

    float mx = v[0];
    #pragma unroll
    for (int i = 1; i < 16; i++) mx = fmaxf(mx, v[i]);
    float ss = 0.f;
    #pragma unroll
    for (int i = 0; i < 16; i++) ss += __expf(v[i] - mx);

    if (h == 1) { sMx[nl] = mx; sSs[nl] = ss; }
    __syncthreads();
    if (h == 0) {
        float mx1 = sMx[nl], ss1 = sSs[nl];
        float M = fmaxf(mx, mx1);
        float S = ss * __expf(mx - M) + ss1 * __expf(mx1 - M);
        out[blockIdx.x * 128 + nl] = M + __logf(S);
    }
}

// ---------------------------------------------------------------------------
extern "C" void kernel_launch(void* const* d_in, const int* in_sizes, int n_in,
                              void* d_out, int out_size) {
    const float *x = 0, *mu = 0, *cov = 0, *w = 0;
    for (int i = 0; i < n_in; i++) {
        long s = in_sizes[i];
        const float* p = (const float*)d_in[i];
        if      (s == (long)Nn * Dd)      x   = p;
        else if (s == (long)Kc * Dd * Dd) cov = p;
        else if (s == (long)Kc * Dd)      mu  = p;
        else if (s == (long)Kc)           w   = p;
    }

    const int p12_smem = (Dd * EP + 32 * EP + Dd) * (int)sizeof(float);
    cudaFuncSetAttribute(prep12,   cudaFuncAttributeMaxDynamicSharedMemorySize, p12_smem);
    cudaFuncSetAttribute(gmm_main, cudaFuncAttributeMaxDynamicSharedMemorySize, SMEM_MAIN);

    prep12<<<dim3(Kc, 4), 256, p12_smem>>>(cov, mu);
    gmm_main<<<dim3(NCTA, KSPL), 256, SMEM_MAIN>>>(x);
    lse_kernel<<<NCTA, 256>>>(w, (float*)d_out);
}

// round 15
// speedup vs baseline: 1.0088x; 1.0088x over previous
#include <cuda_runtime.h>
#include <cuda_fp16.h>
#include <math.h>
#include <stdint.h>

#define Kc 32
#define Dd 128
#define Nn 65536
#define EPSc 1e-6f
#define NCTA (Nn / 128)
#define KSPL 2
#define KPC  (Kc / KSPL)   // components per CTA
#define NSLAB 8            // prep slabs per k (16 rows each)

// ---------------- device scratch (no allocs allowed) ----------------
__device__ __half g_Ah[Kc * Dd * Dd];   // A = Sigma^{-1/2}, f16, ldmatrix-swizzled
__device__ float  g_b[Kc * Dd];         // b_k = A_k @ mu_k (fp32)
__device__ float  g_tp1[Kc * NSLAB * 2];
__device__ float  g_tp2[Kc * NSLAB * 2];
__device__ float  g_pr[(size_t)Kc * NCTA * 2 * 128];  // maha partials (2 halves)

__device__ __forceinline__ uint32_t sw_off(uint32_t row, uint32_t col) {
    return row * 256u + (((col >> 3) ^ (row & 7u)) << 4) + (col & 7u) * 2u;
}
__device__ __forceinline__ uint32_t s2u(const void* p) {
    uint32_t a;
    asm("{ .reg .u64 t; cvta.to.shared.u64 t, %1; cvt.u32.u64 %0, t; }" : "=r"(a) : "l"(p));
    return a;
}
__device__ __forceinline__ void cpasync16(uint32_t dst, const void* src) {
    asm volatile("cp.async.cg.shared.global [%0], [%1], 16;" :: "r"(dst), "l"(src));
}
#define CP_COMMIT() asm volatile("cp.async.commit_group;" ::: "memory")
#define CP_WAIT1()  asm volatile("cp.async.wait_group 1;" ::: "memory")

__device__ __forceinline__ void ldsm4(uint32_t* r, uint32_t a) {
    asm volatile("ldmatrix.sync.aligned.m8n8.x4.shared.b16 {%0,%1,%2,%3}, [%4];"
        : "=r"(r[0]), "=r"(r[1]), "=r"(r[2]), "=r"(r[3]) : "r"(a));
}
__device__ __forceinline__ void ldsm4t(uint32_t* r, uint32_t a) {
    asm volatile("ldmatrix.sync.aligned.m8n8.x4.trans.shared.b16 {%0,%1,%2,%3}, [%4];"
        : "=r"(r[0]), "=r"(r[1]), "=r"(r[2]), "=r"(r[3]) : "r"(a));
}
__device__ __forceinline__ void mma16816(float* d, const uint32_t* a, const uint32_t* b) {
    asm volatile("mma.sync.aligned.m16n8k16.row.col.f32.f16.f16.f32 "
        "{%0,%1,%2,%3}, {%4,%5,%6,%7}, {%8,%9}, {%0,%1,%2,%3};"
        : "+f"(d[0]), "+f"(d[1]), "+f"(d[2]), "+f"(d[3])
        : "r"(a[0]), "r"(a[1]), "r"(a[2]), "r"(a[3]), "r"(b[0]), "r"(b[1]));
}

__device__ __forceinline__ void cta_red2(float& a, float& b, float* aux) {
    #pragma unroll
    for (int o = 16; o > 0; o >>= 1) {
        a += __shfl_xor_sync(0xffffffffu, a, o);
        b += __shfl_xor_sync(0xffffffffu, b, o);
    }
    int w = threadIdx.x >> 5, l = threadIdx.x & 31;
    if (l == 0) { aux[w] = a; aux[8 + w] = b; }
    __syncthreads();
    if (threadIdx.x == 0) {
        a = 0.f; b = 0.f;
        #pragma unroll
        for (int i = 0; i < 8; i++) { a += aux[i]; b += aux[8 + i]; }
    }
}

#define EP 132

// ---------------------------------------------------------------------------
// Fused prep: grid (Kc, NSLAB). Slab = 16 rows, thread tile 2x4.
// E2 slab in regs->smem; E3 slab; A = I + S f16 swizzled; b = A mu; traces.
// 256 blocks, ~75KB smem -> 2 CTA/SM.
// ---------------------------------------------------------------------------
__global__ __launch_bounds__(256) void prep12(const float* __restrict__ cov,
                                              const float* __restrict__ mu) {
    extern __shared__ float sh2[];
    float* sE  = sh2;                    // [128][EP]
    float* sE2 = sh2 + Dd * EP;          // [16][EP]
    float* sMu = sE2 + 16 * EP;          // [128]
    __shared__ float aux[16];
    const int k = blockIdx.x, slab = blockIdx.y * 16;
    const int tid = threadIdx.x;
    const float* ck = cov + (size_t)k * Dd * Dd;

    for (int idx = tid; idx < Dd * Dd; idx += 256) {
        int i = idx >> 7, j = idx & 127;
        sE[i * EP + j] = ck[idx] - (i == j ? (1.f - EPSc) : 0.f);
    }
    if (tid < Dd) sMu[tid] = mu[k * Dd + tid];
    __syncthreads();

    // traces t1, t2 over slab rows (16*128 elems)
    float t1 = 0.f, t2 = 0.f;
    for (int idx = tid; idx < 16 * Dd; idx += 256) {
        int i = slab + (idx >> 7), j = idx & 127;
        float e = sE[i * EP + j];
        t2 += e * e;
        if (i == j) t1 += e;
    }

    const int ti = tid >> 5, tj = tid & 31;
    const int r0 = ti * 2, j0 = tj * 4;      // slab-local rows (2), global cols (4)

    // ---- E2 slab = E|slab * E ----
    float acc2[2][4];
    #pragma unroll
    for (int a = 0; a < 2; a++)
        #pragma unroll
        for (int b = 0; b < 4; b++) acc2[a][b] = 0.f;
    for (int m = 0; m < Dd; m++) {
        float4 bv = *(const float4*)&sE[m * EP + j0];
        #pragma unroll
        for (int a = 0; a < 2; a++) {
            float av = sE[(slab + r0 + a) * EP + m];
            acc2[a][0] = fmaf(av, bv.x, acc2[a][0]);
            acc2[a][1] = fmaf(av, bv.y, acc2[a][1]);
            acc2[a][2] = fmaf(av, bv.z, acc2[a][2]);
            acc2[a][3] = fmaf(av, bv.w, acc2[a][3]);
        }
    }
    // traces t3, t4 from acc2
    float t3 = 0.f, t4 = 0.f;
    #pragma unroll
    for (int a = 0; a < 2; a++)
        #pragma unroll
        for (int b = 0; b < 4; b++) {
            float e2 = acc2[a][b];
            t3 += e2 * sE[(slab + r0 + a) * EP + j0 + b];
            t4 += e2 * e2;
        }
    #pragma unroll
    for (int a = 0; a < 2; a++)
        *(float4*)&sE2[(r0 + a) * EP + j0] =
            make_float4(acc2[a][0], acc2[a][1], acc2[a][2], acc2[a][3]);
    __syncthreads();

    // ---- E3 slab = E2|slab * E ----
    float acc3[2][4];
    #pragma unroll
    for (int a = 0; a < 2; a++)
        #pragma unroll
        for (int b = 0; b < 4; b++) acc3[a][b] = 0.f;
    for (int m = 0; m < Dd; m++) {
        float4 bv = *(const float4*)&sE[m * EP + j0];
        #pragma unroll
        for (int a = 0; a < 2; a++) {
            float av = sE2[(r0 + a) * EP + m];
            acc3[a][0] = fmaf(av, bv.x, acc3[a][0]);
            acc3[a][1] = fmaf(av, bv.y, acc3[a][1]);
            acc3[a][2] = fmaf(av, bv.z, acc3[a][2]);
            acc3[a][3] = fmaf(av, bv.w, acc3[a][3]);
        }
    }

    // ---- A = I - E/2 + 3/8 E2 - 5/16 E3 ; f16 swizzled; b partials ----
    __half* Ak = g_Ah + (size_t)k * Dd * Dd;
    float rb[2] = {0.f, 0.f};
    #pragma unroll
    for (int a = 0; a < 2; a++) {
        int i = slab + r0 + a;
        #pragma unroll
        for (int b = 0; b < 4; b++) {
            int j = j0 + b;
            float e  = sE[i * EP + j];
            float v = ((i == j) ? 1.f : 0.f) - 0.5f * e + 0.375f * acc2[a][b]
                      - 0.3125f * acc3[a][b];
            Ak[sw_off((uint32_t)i, (uint32_t)j) >> 1] = __float2half(v);
            rb[a] = fmaf(v, sMu[j], rb[a]);
        }
    }
    #pragma unroll
    for (int a = 0; a < 2; a++) {
        #pragma unroll
        for (int o = 16; o > 0; o >>= 1)
            rb[a] += __shfl_xor_sync(0xffffffffu, rb[a], o);
        if (tj == 0) g_b[k * Dd + slab + r0 + a] = rb[a];
    }

    cta_red2(t1, t2, aux);
    if (tid == 0) {
        g_tp1[(k * NSLAB + blockIdx.y) * 2 + 0] = t1;
        g_tp1[(k * NSLAB + blockIdx.y) * 2 + 1] = t2;
    }
    __syncthreads();
    cta_red2(t3, t4, aux);
    if (tid == 0) {
        g_tp2[(k * NSLAB + blockIdx.y) * 2 + 0] = t3;
        g_tp2[(k * NSLAB + blockIdx.y) * 2 + 1] = t4;
    }
}

// ---------------------------------------------------------------------------
// Main: grid (NCTA, KSPL); A staged in pairs; prologue before X convert.
// ---------------------------------------------------------------------------
#define XS_OFF 0
#define A0_OFF 32768           // pair buffer 0: 64KB
#define A1_OFF 98304           // pair buffer 1: 64KB
#define BS_OFF 163840          // KPC*Dd fp32 = 8KB
#define SMEM_MAIN 172032

__device__ __forceinline__ void loadB(uint32_t bbuf[8][2], uint32_t ab, int ks,
                                      int wn, int l) {
    #pragma unroll
    for (int p = 0; p < 4; p++) {
        uint32_t tmp[4];
        int row = wn * 64 + p * 16 + ((l >> 4) << 3) + (l & 7);
        int ch  = ks * 2 + ((l >> 3) & 1);
        ldsm4t(tmp, ab + (uint32_t)(row * 256 + ((ch ^ (row & 7)) << 4)));
        bbuf[p*2][0]   = tmp[0]; bbuf[p*2][1]   = tmp[1];
        bbuf[p*2+1][0] = tmp[2]; bbuf[p*2+1][1] = tmp[3];
    }
}

__global__ void __launch_bounds__(256, 1) gmm_main(const float* __restrict__ x) {
    extern __shared__ char sm[];
    const uint32_t smb = s2u(sm);
    const int tid = threadIdx.x;
    const int wid = tid >> 5, l = tid & 31;
    const int wm = wid & 3, wn = wid >> 2;
    const int n0 = blockIdx.x * 128;
    const int k0 = blockIdx.y * KPC;

    float* bs = (float*)(sm + BS_OFF);

    // Prologue FIRST: pair (k0, k0+1) -> buf0; latency hides behind X convert.
    for (int ch = tid; ch < 4096; ch += 256)
        cpasync16(smb + A0_OFF + ch * 16, (const char*)g_Ah + (size_t)k0 * 32768 + ch * 16);
    CP_COMMIT();

    // X tile -> f16 swizzled SMEM
    for (int ch = tid; ch < 2048; ch += 256) {
        int row = ch >> 4, cc = (ch & 15) * 8;
        const float4* src = (const float4*)(x + (size_t)(n0 + row) * Dd + cc);
        float4 u = src[0], v = src[1];
        __half2 h[4] = { __floats2half2_rn(u.x, u.y), __floats2half2_rn(u.z, u.w),
                         __floats2half2_rn(v.x, v.y), __floats2half2_rn(v.z, v.w) };
        *(uint4*)(sm + XS_OFF + sw_off((uint32_t)row, (uint32_t)cc)) = *(uint4*)h;
    }
    for (int i = tid; i < KPC * Dd; i += 256) bs[i] = g_b[k0 * Dd + i];
    __syncthreads();

    // Preload X fragments: 2 m-tiles x 8 k-steps, register resident.
    uint32_t xa[2][8][4];
    #pragma unroll
    for (int mt = 0; mt < 2; mt++)
        #pragma unroll
        for (int ks = 0; ks < 8; ks++) {
            int row = wm * 32 + mt * 16 + (l & 15);
            int ch  = ks * 2 + (l >> 4);
            ldsm4(xa[mt][ks], smb + XS_OFF + (uint32_t)(row * 256 + ((ch ^ (row & 7)) << 4)));
        }

    // partial-store base: [k][cta][wn][128]
    float* prb = g_pr + ((size_t)blockIdx.x * 2 + wn) * 128 + wm * 32 + (l >> 2);

    for (int kp = 0; kp < KPC; kp += 2) {
        __syncthreads();  // all warps done reading the buffer being overwritten
        {   // prefetch next pair
            int kn = k0 + ((kp + 2) & (KPC - 1));
            const char* src = (const char*)g_Ah + (size_t)kn * 32768;
            uint32_t dst = smb + ((((kp >> 1) + 1) & 1) ? A1_OFF : A0_OFF);
            for (int ch = tid; ch < 4096; ch += 256)
                cpasync16(dst + ch * 16, src + ch * 16);
            CP_COMMIT();
        }
        CP_WAIT1();
        __syncthreads();  // current pair visible

        const uint32_t pb = smb + (((kp >> 1) & 1) ? A1_OFF : A0_OFF);

        #pragma unroll
        for (int s = 0; s < 2; s++) {
            const int kk = kp + s;
            const int k = k0 + kk;
            const uint32_t ab = pb + s * 32768;

            float acc[2][8][4];
            #pragma unroll
            for (int mt = 0; mt < 2; mt++)
                #pragma unroll
                for (int nt = 0; nt < 8; nt++)
                    #pragma unroll
                    for (int e = 0; e < 4; e++) acc[mt][nt][e] = 0.f;

            uint32_t bb[2][8][2];
            loadB(bb[0], ab, 0, wn, l);
            #pragma unroll
            for (int ks = 0; ks < 8; ks++) {
                if (ks < 7) loadB(bb[(ks + 1) & 1], ab, ks + 1, wn, l);
                #pragma unroll
                for (int mt = 0; mt < 2; mt++)
                    #pragma unroll
                    for (int nt = 0; nt < 8; nt++)
                        mma16816(acc[mt][nt], xa[mt][ks], bb[ks & 1][nt]);
            }

            float pr[4] = {0.f, 0.f, 0.f, 0.f};
            #pragma unroll
            for (int nt = 0; nt < 8; nt++) {
                int d0 = wn * 64 + nt * 8 + (l & 3) * 2;
                float b0 = bs[kk * Dd + d0], b1 = bs[kk * Dd + d0 + 1];
                #pragma unroll
                for (int mt = 0; mt < 2; mt++) {
                    float t0 = acc[mt][nt][0] - b0, t1 = acc[mt][nt][1] - b1;
                    pr[mt*2]   = fmaf(t0, t0, fmaf(t1, t1, pr[mt*2]));
                    float t2 = acc[mt][nt][2] - b0, t3 = acc[mt][nt][3] - b1;
                    pr[mt*2+1] = fmaf(t2, t2, fmaf(t3, t3, pr[mt*2+1]));
                }
            }
            #pragma unroll
            for (int q = 0; q < 4; q++) {
                pr[q] += __shfl_xor_sync(0xffffffffu, pr[q], 1);
                pr[q] += __shfl_xor_sync(0xffffffffu, pr[q], 2);
            }
            if ((l & 3) == 0) {
                float* pk = prb + (size_t)k * NCTA * 2 * 128;
                pk[0]  = pr[0];
                pk[8]  = pr[1];
                pk[16] = pr[2];
                pk[24] = pr[3];
            }
        }
    }
}

// ---------------------------------------------------------------------------
// LSE kernel: grid NCTA, block 256 = 128 samples x 2 k-halves. Folds cst
// computation from trace partials (L2-hot). Split-k: 32 loads/thread, full MLP.
// ---------------------------------------------------------------------------
__global__ __launch_bounds__(256) void lse_kernel(const float* __restrict__ w,
                                                  float* __restrict__ out) {
    __shared__ float cs[Kc];
    __shared__ float sMx[128], sSs[128];
    const int tid = threadIdx.x;

    if (tid < Kc) {   // cst[k] from trace partials
        int k = tid;
        float t1 = 0.f, t2 = 0.f, t3 = 0.f, t4 = 0.f;
        #pragma unroll
        for (int s = 0; s < NSLAB; s++) {
            t1 += g_tp1[(k * NSLAB + s) * 2 + 0];
            t2 += g_tp1[(k * NSLAB + s) * 2 + 1];
            t3 += g_tp2[(k * NSLAB + s) * 2 + 0];
            t4 += g_tp2[(k * NSLAB + s) * 2 + 1];
        }
        float hld = 0.5f * (t1 - 0.5f * t2 + t3 / 3.f - 0.25f * t4);
        cs[k] = -0.5f * (float)Dd * 1.8378770664093453f - hld + logf(w[k]);
    }
    __syncthreads();

    const int h = tid >> 7, nl = tid & 127;
    const float* p = g_pr + (size_t)blockIdx.x * 256 + nl;

    float v[16];
    #pragma unroll
    for (int i = 0; i < 16; i++) {
        const float* pk = p + (size_t)(h * 16 + i) * NCTA * 256;
        v[i] = pk[0] + pk[128];          // independent loads -> front-batched
    }
    #pragma unroll
    for (int i = 0; i < 16; i++)
        v[i] = cs[h * 16 + i] - 0.5f * v[i];

    float mx = v[0];
    #pragma unroll
    for (int i = 1; i < 16; i++) mx = fmaxf(mx, v[i]);
    float ss = 0.f;
    #pragma unroll
    for (int i = 0; i < 16; i++) ss += __expf(v[i] - mx);

    if (h == 1) { sMx[nl] = mx; sSs[nl] = ss; }
    __syncthreads();
    if (h == 0) {
        float mx1 = sMx[nl], ss1 = sSs[nl];
        float M = fmaxf(mx, mx1);
        float S = ss * __expf(mx - M) + ss1 * __expf(mx1 - M);
        out[blockIdx.x * 128 + nl] = M + __logf(S);
    }
}

// ---------------------------------------------------------------------------
extern "C" void kernel_launch(void* const* d_in, const int* in_sizes, int n_in,
                              void* d_out, int out_size) {
    const float *x = 0, *mu = 0, *cov = 0, *w = 0;
    for (int i = 0; i < n_in; i++) {
        long s = in_sizes[i];
        const float* p = (const float*)d_in[i];
        if      (s == (long)Nn * Dd)      x   = p;
        else if (s == (long)Kc * Dd * Dd) cov = p;
        else if (s == (long)Kc * Dd)      mu  = p;
        else if (s == (long)Kc)           w   = p;
    }

    const int p12_smem = (Dd * EP + 16 * EP + Dd) * (int)sizeof(float);  // ~76KB
    cudaFuncSetAttribute(prep12,   cudaFuncAttributeMaxDynamicSharedMemorySize, p12_smem);
    cudaFuncSetAttribute(gmm_main, cudaFuncAttributeMaxDynamicSharedMemorySize, SMEM_MAIN);

    prep12<<<dim3(Kc, NSLAB), 256, p12_smem>>>(cov, mu);
    gmm_main<<<dim3(NCTA, KSPL), 256, SMEM_MAIN>>>(x);
    lse_kernel<<<NCTA, 256>>>(w, (float*)d_out);
}

// round 16
// speedup vs baseline: 1.0411x; 1.0320x over previous
#include <cuda_runtime.h>
#include <cuda_fp16.h>
#include <math.h>
#include <stdint.h>

#define Kc 32
#define Dd 128
#define Nn 65536
#define EPSc 1e-6f
#define NCTA (Nn / 128)
#define KSPL 2
#define KPC  (Kc / KSPL)   // components per CTA

// ---------------- device scratch (no allocs allowed) ----------------
__device__ __half g_Ah[Kc * Dd * Dd];   // A = Sigma^{-1/2} (quadratic series), f16, swizzled
__device__ float  g_b[Kc * Dd];         // b_k = A_k @ mu_k (fp32)
__device__ float  g_cst[Kc];            // -0.5*D*log(2pi) - half_logdet + log(w)
__device__ float  g_tp1[Kc * 4 * 2];
__device__ float  g_tp2[Kc * 4 * 2];
__device__ float  g_pr[(size_t)Kc * NCTA * 2 * 128];  // maha partials (2 halves)

__device__ __forceinline__ uint32_t sw_off(uint32_t row, uint32_t col) {
    return row * 256u + (((col >> 3) ^ (row & 7u)) << 4) + (col & 7u) * 2u;
}
__device__ __forceinline__ uint32_t s2u(const void* p) {
    uint32_t a;
    asm("{ .reg .u64 t; cvta.to.shared.u64 t, %1; cvt.u32.u64 %0, t; }" : "=r"(a) : "l"(p));
    return a;
}
__device__ __forceinline__ void cpasync16(uint32_t dst, const void* src) {
    asm volatile("cp.async.cg.shared.global [%0], [%1], 16;" :: "r"(dst), "l"(src));
}
#define CP_COMMIT() asm volatile("cp.async.commit_group;" ::: "memory")
#define CP_WAIT1()  asm volatile("cp.async.wait_group 1;" ::: "memory")

__device__ __forceinline__ void ldsm4(uint32_t* r, uint32_t a) {
    asm volatile("ldmatrix.sync.aligned.m8n8.x4.shared.b16 {%0,%1,%2,%3}, [%4];"
        : "=r"(r[0]), "=r"(r[1]), "=r"(r[2]), "=r"(r[3]) : "r"(a));
}
__device__ __forceinline__ void ldsm4t(uint32_t* r, uint32_t a) {
    asm volatile("ldmatrix.sync.aligned.m8n8.x4.trans.shared.b16 {%0,%1,%2,%3}, [%4];"
        : "=r"(r[0]), "=r"(r[1]), "=r"(r[2]), "=r"(r[3]) : "r"(a));
}
__device__ __forceinline__ void mma16816(float* d, const uint32_t* a, const uint32_t* b) {
    asm volatile("mma.sync.aligned.m16n8k16.row.col.f32.f16.f16.f32 "
        "{%0,%1,%2,%3}, {%4,%5,%6,%7}, {%8,%9}, {%0,%1,%2,%3};"
        : "+f"(d[0]), "+f"(d[1]), "+f"(d[2]), "+f"(d[3])
        : "r"(a[0]), "r"(a[1]), "r"(a[2]), "r"(a[3]), "r"(b[0]), "r"(b[1]));
}

__device__ __forceinline__ void cta_red2(float& a, float& b, float* aux) {
    #pragma unroll
    for (int o = 16; o > 0; o >>= 1) {
        a += __shfl_xor_sync(0xffffffffu, a, o);
        b += __shfl_xor_sync(0xffffffffu, b, o);
    }
    int w = threadIdx.x >> 5, l = threadIdx.x & 31;
    if (l == 0) { aux[w] = a; aux[8 + w] = b; }
    __syncthreads();
    if (threadIdx.x == 0) {
        a = 0.f; b = 0.f;
        #pragma unroll
        for (int i = 0; i < 8; i++) { a += aux[i]; b += aux[8 + i]; }
    }
}

#define EP 132

// ---------------------------------------------------------------------------
// Fused prep (quadratic series): grid (Kc, 4), slab = 32 rows, tile 4x4.
// One GEMM only: E2 = E|slab * E. A = I - E/2 + 3/8 E2 (f16 swizzled);
// traces t1..t4 (t3, t4 elementwise from E2 accumulators); b = A mu.
// ---------------------------------------------------------------------------
__global__ __launch_bounds__(256) void prep12(const float* __restrict__ cov,
                                              const float* __restrict__ mu) {
    extern __shared__ float sh2[];
    float* sE  = sh2;                    // [128][EP]
    float* sMu = sh2 + Dd * EP;          // [128]
    __shared__ float aux[16];
    const int k = blockIdx.x, slab = blockIdx.y * 32;
    const int tid = threadIdx.x;
    const float* ck = cov + (size_t)k * Dd * Dd;

    for (int idx = tid; idx < Dd * Dd; idx += 256) {
        int i = idx >> 7, j = idx & 127;
        sE[i * EP + j] = ck[idx] - (i == j ? (1.f - EPSc) : 0.f);
    }
    if (tid < Dd) sMu[tid] = mu[k * Dd + tid];
    __syncthreads();

    // traces t1, t2 over slab rows
    float t1 = 0.f, t2 = 0.f;
    for (int idx = tid; idx < 32 * Dd; idx += 256) {
        int i = slab + (idx >> 7), j = idx & 127;
        float e = sE[i * EP + j];
        t2 += e * e;
        if (i == j) t1 += e;
    }

    const int ti = tid >> 5, tj = tid & 31;
    const int r0 = ti * 4, j0 = tj * 4;      // slab-local rows, global cols

    // ---- single GEMM: E2 slab = E|slab * E ----
    float acc2[4][4];
    #pragma unroll
    for (int a = 0; a < 4; a++)
        #pragma unroll
        for (int b = 0; b < 4; b++) acc2[a][b] = 0.f;
    for (int m = 0; m < Dd; m++) {
        float4 bv = *(const float4*)&sE[m * EP + j0];
        #pragma unroll
        for (int a = 0; a < 4; a++) {
            float av = sE[(slab + r0 + a) * EP + m];
            acc2[a][0] = fmaf(av, bv.x, acc2[a][0]);
            acc2[a][1] = fmaf(av, bv.y, acc2[a][1]);
            acc2[a][2] = fmaf(av, bv.z, acc2[a][2]);
            acc2[a][3] = fmaf(av, bv.w, acc2[a][3]);
        }
    }
    // traces t3 = <E2, E>, t4 = ||E2||^2 — elementwise, no E3 GEMM needed
    float t3 = 0.f, t4 = 0.f;
    #pragma unroll
    for (int a = 0; a < 4; a++)
        #pragma unroll
        for (int b = 0; b < 4; b++) {
            float e2 = acc2[a][b];
            t3 += e2 * sE[(slab + r0 + a) * EP + j0 + b];
            t4 += e2 * e2;
        }

    // ---- A = I - E/2 + 3/8 E2 (cubic term dropped; error ~3e-5 << f16) ----
    __half* Ak = g_Ah + (size_t)k * Dd * Dd;
    float rb[4] = {0.f, 0.f, 0.f, 0.f};
    #pragma unroll
    for (int a = 0; a < 4; a++) {
        int i = slab + r0 + a;
        #pragma unroll
        for (int b = 0; b < 4; b++) {
            int j = j0 + b;
            float e = sE[i * EP + j];
            float v = ((i == j) ? 1.f : 0.f) - 0.5f * e + 0.375f * acc2[a][b];
            Ak[sw_off((uint32_t)i, (uint32_t)j) >> 1] = __float2half(v);
            rb[a] = fmaf(v, sMu[j], rb[a]);
        }
    }
    #pragma unroll
    for (int a = 0; a < 4; a++) {
        #pragma unroll
        for (int o = 16; o > 0; o >>= 1)
            rb[a] += __shfl_xor_sync(0xffffffffu, rb[a], o);
        if (tj == 0) g_b[k * Dd + slab + r0 + a] = rb[a];
    }

    cta_red2(t1, t2, aux);
    if (tid == 0) {
        g_tp1[(k * 4 + blockIdx.y) * 2 + 0] = t1;
        g_tp1[(k * 4 + blockIdx.y) * 2 + 1] = t2;
    }
    __syncthreads();
    cta_red2(t3, t4, aux);
    if (tid == 0) {
        g_tp2[(k * 4 + blockIdx.y) * 2 + 0] = t3;
        g_tp2[(k * 4 + blockIdx.y) * 2 + 1] = t4;
    }
}

// ---------------------------------------------------------------------------
// P3: cst[k] from trace partials.
// ---------------------------------------------------------------------------
__global__ void prep3(const float* __restrict__ w) {
    int k = threadIdx.x;
    if (k >= Kc) return;
    float t1 = 0.f, t2 = 0.f, t3 = 0.f, t4 = 0.f;
    #pragma unroll
    for (int s = 0; s < 4; s++) {
        t1 += g_tp1[(k * 4 + s) * 2 + 0];
        t2 += g_tp1[(k * 4 + s) * 2 + 1];
        t3 += g_tp2[(k * 4 + s) * 2 + 0];
        t4 += g_tp2[(k * 4 + s) * 2 + 1];
    }
    float hld = 0.5f * (t1 - 0.5f * t2 + t3 / 3.f - 0.25f * t4);
    g_cst[k] = -0.5f * (float)Dd * 1.8378770664093453f - hld + logf(w[k]);
}

// ---------------------------------------------------------------------------
// Main: grid (NCTA, KSPL); A staged in pairs; prologue before X convert.
// (Unchanged from the 215.8us best.)
// ---------------------------------------------------------------------------
#define XS_OFF 0
#define A0_OFF 32768           // pair buffer 0: 64KB
#define A1_OFF 98304           // pair buffer 1: 64KB
#define BS_OFF 163840          // KPC*Dd fp32 = 8KB
#define SMEM_MAIN 172032

__device__ __forceinline__ void loadB(uint32_t bbuf[8][2], uint32_t ab, int ks,
                                      int wn, int l) {
    #pragma unroll
    for (int p = 0; p < 4; p++) {
        uint32_t tmp[4];
        int row = wn * 64 + p * 16 + ((l >> 4) << 3) + (l & 7);
        int ch  = ks * 2 + ((l >> 3) & 1);
        ldsm4t(tmp, ab + (uint32_t)(row * 256 + ((ch ^ (row & 7)) << 4)));
        bbuf[p*2][0]   = tmp[0]; bbuf[p*2][1]   = tmp[1];
        bbuf[p*2+1][0] = tmp[2]; bbuf[p*2+1][1] = tmp[3];
    }
}

__global__ void __launch_bounds__(256, 1) gmm_main(const float* __restrict__ x) {
    extern __shared__ char sm[];
    const uint32_t smb = s2u(sm);
    const int tid = threadIdx.x;
    const int wid = tid >> 5, l = tid & 31;
    const int wm = wid & 3, wn = wid >> 2;
    const int n0 = blockIdx.x * 128;
    const int k0 = blockIdx.y * KPC;

    float* bs = (float*)(sm + BS_OFF);

    // Prologue FIRST: pair (k0, k0+1) -> buf0; latency hides behind X convert.
    for (int ch = tid; ch < 4096; ch += 256)
        cpasync16(smb + A0_OFF + ch * 16, (const char*)g_Ah + (size_t)k0 * 32768 + ch * 16);
    CP_COMMIT();

    // X tile -> f16 swizzled SMEM
    for (int ch = tid; ch < 2048; ch += 256) {
        int row = ch >> 4, cc = (ch & 15) * 8;
        const float4* src = (const float4*)(x + (size_t)(n0 + row) * Dd + cc);
        float4 u = src[0], v = src[1];
        __half2 h[4] = { __floats2half2_rn(u.x, u.y), __floats2half2_rn(u.z, u.w),
                         __floats2half2_rn(v.x, v.y), __floats2half2_rn(v.z, v.w) };
        *(uint4*)(sm + XS_OFF + sw_off((uint32_t)row, (uint32_t)cc)) = *(uint4*)h;
    }
    for (int i = tid; i < KPC * Dd; i += 256) bs[i] = g_b[k0 * Dd + i];
    __syncthreads();

    // Preload X fragments: 2 m-tiles x 8 k-steps, register resident.
    uint32_t xa[2][8][4];
    #pragma unroll
    for (int mt = 0; mt < 2; mt++)
        #pragma unroll
        for (int ks = 0; ks < 8; ks++) {
            int row = wm * 32 + mt * 16 + (l & 15);
            int ch  = ks * 2 + (l >> 4);
            ldsm4(xa[mt][ks], smb + XS_OFF + (uint32_t)(row * 256 + ((ch ^ (row & 7)) << 4)));
        }

    // partial-store base: [k][cta][wn][128]
    float* prb = g_pr + ((size_t)blockIdx.x * 2 + wn) * 128 + wm * 32 + (l >> 2);

    for (int kp = 0; kp < KPC; kp += 2) {
        __syncthreads();  // all warps done reading the buffer being overwritten
        {   // prefetch next pair
            int kn = k0 + ((kp + 2) & (KPC - 1));
            const char* src = (const char*)g_Ah + (size_t)kn * 32768;
            uint32_t dst = smb + ((((kp >> 1) + 1) & 1) ? A1_OFF : A0_OFF);
            for (int ch = tid; ch < 4096; ch += 256)
                cpasync16(dst + ch * 16, src + ch * 16);
            CP_COMMIT();
        }
        CP_WAIT1();
        __syncthreads();  // current pair visible

        const uint32_t pb = smb + (((kp >> 1) & 1) ? A1_OFF : A0_OFF);

        #pragma unroll
        for (int s = 0; s < 2; s++) {
            const int kk = kp + s;
            const int k = k0 + kk;
            const uint32_t ab = pb + s * 32768;

            float acc[2][8][4];
            #pragma unroll
            for (int mt = 0; mt < 2; mt++)
                #pragma unroll
                for (int nt = 0; nt < 8; nt++)
                    #pragma unroll
                    for (int e = 0; e < 4; e++) acc[mt][nt][e] = 0.f;

            uint32_t bb[2][8][2];
            loadB(bb[0], ab, 0, wn, l);
            #pragma unroll
            for (int ks = 0; ks < 8; ks++) {
                if (ks < 7) loadB(bb[(ks + 1) & 1], ab, ks + 1, wn, l);
                #pragma unroll
                for (int mt = 0; mt < 2; mt++)
                    #pragma unroll
                    for (int nt = 0; nt < 8; nt++)
                        mma16816(acc[mt][nt], xa[mt][ks], bb[ks & 1][nt]);
            }

            float pr[4] = {0.f, 0.f, 0.f, 0.f};
            #pragma unroll
            for (int nt = 0; nt < 8; nt++) {
                int d0 = wn * 64 + nt * 8 + (l & 3) * 2;
                float b0 = bs[kk * Dd + d0], b1 = bs[kk * Dd + d0 + 1];
                #pragma unroll
                for (int mt = 0; mt < 2; mt++) {
                    float t0 = acc[mt][nt][0] - b0, t1 = acc[mt][nt][1] - b1;
                    pr[mt*2]   = fmaf(t0, t0, fmaf(t1, t1, pr[mt*2]));
                    float t2 = acc[mt][nt][2] - b0, t3 = acc[mt][nt][3] - b1;
                    pr[mt*2+1] = fmaf(t2, t2, fmaf(t3, t3, pr[mt*2+1]));
                }
            }
            #pragma unroll
            for (int q = 0; q < 4; q++) {
                pr[q] += __shfl_xor_sync(0xffffffffu, pr[q], 1);
                pr[q] += __shfl_xor_sync(0xffffffffu, pr[q], 2);
            }
            if ((l & 3) == 0) {
                float* pk = prb + (size_t)k * NCTA * 2 * 128;
                pk[0]  = pr[0];
                pk[8]  = pr[1];
                pk[16] = pr[2];
                pk[24] = pr[3];
            }
        }
    }
}

// ---------------------------------------------------------------------------
// LSE kernel, two-pass (R13 version): batch-load all 32 m_k, max-tree + sum.
// ---------------------------------------------------------------------------
__global__ __launch_bounds__(256) void lse_kernel(float* __restrict__ out) {
    __shared__ float cs[Kc];
    if (threadIdx.x < Kc) cs[threadIdx.x] = g_cst[threadIdx.x];
    __syncthreads();
    const int n = blockIdx.x * 256 + threadIdx.x;
    const int cta = n >> 7, nl = n & 127;
    const float* p = g_pr + (size_t)cta * 2 * 128 + nl;

    float v[Kc];
    #pragma unroll
    for (int k = 0; k < Kc; k++) {
        const float* pk = p + (size_t)k * NCTA * 2 * 128;
        v[k] = pk[0] + pk[128];          // independent loads -> front-batched
    }
    #pragma unroll
    for (int k = 0; k < Kc; k++)
        v[k] = cs[k] - 0.5f * v[k];

    float mx = v[0];
    #pragma unroll
    for (int k = 1; k < Kc; k++) mx = fmaxf(mx, v[k]);
    float ss = 0.f;
    #pragma unroll
    for (int k = 0; k < Kc; k++) ss += __expf(v[k] - mx);
    out[n] = mx + __logf(ss);
}

// ---------------------------------------------------------------------------
extern "C" void kernel_launch(void* const* d_in, const int* in_sizes, int n_in,
                              void* d_out, int out_size) {
    const float *x = 0, *mu = 0, *cov = 0, *w = 0;
    for (int i = 0; i < n_in; i++) {
        long s = in_sizes[i];
        const float* p = (const float*)d_in[i];
        if      (s == (long)Nn * Dd)      x   = p;
        else if (s == (long)Kc * Dd * Dd) cov = p;
        else if (s == (long)Kc * Dd)      mu  = p;
        else if (s == (long)Kc)           w   = p;
    }

    const int p12_smem = (Dd * EP + Dd) * (int)sizeof(float);   // ~68KB
    cudaFuncSetAttribute(prep12,   cudaFuncAttributeMaxDynamicSharedMemorySize, p12_smem);
    cudaFuncSetAttribute(gmm_main, cudaFuncAttributeMaxDynamicSharedMemorySize, SMEM_MAIN);

    prep12<<<dim3(Kc, 4), 256, p12_smem>>>(cov, mu);
    prep3<<<1, 32>>>(w);
    gmm_main<<<dim3(NCTA, KSPL), 256, SMEM_MAIN>>>(x);
    lse_kernel<<<Nn / 256, 256>>>((float*)d_out);
}

// round 17
// speedup vs baseline: 1.0460x; 1.0047x over previous
#include <cuda_runtime.h>
#include <cuda_fp16.h>
#include <math.h>
#include <stdint.h>

#define Kc 32
#define Dd 128
#define Nn 65536
#define EPSc 1e-6f
#define NCTA (Nn / 128)
#define KSPL 2
#define KPC  (Kc / KSPL)   // components per CTA

// ---------------- device scratch (no allocs allowed) ----------------
__device__ __half g_Ah[Kc * Dd * Dd];   // A = Sigma^{-1/2} (quadratic series), f16, swizzled
__device__ float  g_b[Kc * Dd];         // b_k = A_k @ mu_k (fp32)
__device__ float  g_cst[Kc];            // -0.5*D*log(2pi) - half_logdet + log(w)
__device__ float  g_tp1[Kc * 4 * 2];
__device__ float  g_tp2[Kc * 4 * 2];
__device__ float  g_pr[(size_t)Kc * NCTA * 128];   // combined maha partials

__device__ __forceinline__ uint32_t sw_off(uint32_t row, uint32_t col) {
    return row * 256u + (((col >> 3) ^ (row & 7u)) << 4) + (col & 7u) * 2u;
}
__device__ __forceinline__ uint32_t s2u(const void* p) {
    uint32_t a;
    asm("{ .reg .u64 t; cvta.to.shared.u64 t, %1; cvt.u32.u64 %0, t; }" : "=r"(a) : "l"(p));
    return a;
}
__device__ __forceinline__ void cpasync16(uint32_t dst, const void* src) {
    asm volatile("cp.async.cg.shared.global [%0], [%1], 16;" :: "r"(dst), "l"(src));
}
#define CP_COMMIT() asm volatile("cp.async.commit_group;" ::: "memory")
#define CP_WAIT1()  asm volatile("cp.async.wait_group 1;" ::: "memory")

__device__ __forceinline__ void ldsm4(uint32_t* r, uint32_t a) {
    asm volatile("ldmatrix.sync.aligned.m8n8.x4.shared.b16 {%0,%1,%2,%3}, [%4];"
        : "=r"(r[0]), "=r"(r[1]), "=r"(r[2]), "=r"(r[3]) : "r"(a));
}
__device__ __forceinline__ void ldsm4t(uint32_t* r, uint32_t a) {
    asm volatile("ldmatrix.sync.aligned.m8n8.x4.trans.shared.b16 {%0,%1,%2,%3}, [%4];"
        : "=r"(r[0]), "=r"(r[1]), "=r"(r[2]), "=r"(r[3]) : "r"(a));
}
__device__ __forceinline__ void mma16816(float* d, const uint32_t* a, const uint32_t* b) {
    asm volatile("mma.sync.aligned.m16n8k16.row.col.f32.f16.f16.f32 "
        "{%0,%1,%2,%3}, {%4,%5,%6,%7}, {%8,%9}, {%0,%1,%2,%3};"
        : "+f"(d[0]), "+f"(d[1]), "+f"(d[2]), "+f"(d[3])
        : "r"(a[0]), "r"(a[1]), "r"(a[2]), "r"(a[3]), "r"(b[0]), "r"(b[1]));
}

__device__ __forceinline__ void cta_red2(float& a, float& b, float* aux) {
    #pragma unroll
    for (int o = 16; o > 0; o >>= 1) {
        a += __shfl_xor_sync(0xffffffffu, a, o);
        b += __shfl_xor_sync(0xffffffffu, b, o);
    }
    int w = threadIdx.x >> 5, l = threadIdx.x & 31;
    if (l == 0) { aux[w] = a; aux[8 + w] = b; }
    __syncthreads();
    if (threadIdx.x == 0) {
        a = 0.f; b = 0.f;
        #pragma unroll
        for (int i = 0; i < 8; i++) { a += aux[i]; b += aux[8 + i]; }
    }
}

#define EP 132

// ---------------------------------------------------------------------------
// Fused prep (quadratic series): grid (Kc, 4), slab = 32 rows, tile 4x4.
// One GEMM: E2 = E|slab * E. A = I - E/2 + 3/8 E2 (f16 swizzled);
// traces t1..t4 (t3, t4 elementwise from E2 accumulators); b = A mu.
// ---------------------------------------------------------------------------
__global__ __launch_bounds__(256) void prep12(const float* __restrict__ cov,
                                              const float* __restrict__ mu) {
    extern __shared__ float sh2[];
    float* sE  = sh2;                    // [128][EP]
    float* sMu = sh2 + Dd * EP;          // [128]
    __shared__ float aux[16];
    const int k = blockIdx.x, slab = blockIdx.y * 32;
    const int tid = threadIdx.x;
    const float* ck = cov + (size_t)k * Dd * Dd;

    for (int idx = tid; idx < Dd * Dd; idx += 256) {
        int i = idx >> 7, j = idx & 127;
        sE[i * EP + j] = ck[idx] - (i == j ? (1.f - EPSc) : 0.f);
    }
    if (tid < Dd) sMu[tid] = mu[k * Dd + tid];
    __syncthreads();

    float t1 = 0.f, t2 = 0.f;
    for (int idx = tid; idx < 32 * Dd; idx += 256) {
        int i = slab + (idx >> 7), j = idx & 127;
        float e = sE[i * EP + j];
        t2 += e * e;
        if (i == j) t1 += e;
    }

    const int ti = tid >> 5, tj = tid & 31;
    const int r0 = ti * 4, j0 = tj * 4;

    float acc2[4][4];
    #pragma unroll
    for (int a = 0; a < 4; a++)
        #pragma unroll
        for (int b = 0; b < 4; b++) acc2[a][b] = 0.f;
    for (int m = 0; m < Dd; m++) {
        float4 bv = *(const float4*)&sE[m * EP + j0];
        #pragma unroll
        for (int a = 0; a < 4; a++) {
            float av = sE[(slab + r0 + a) * EP + m];
            acc2[a][0] = fmaf(av, bv.x, acc2[a][0]);
            acc2[a][1] = fmaf(av, bv.y, acc2[a][1]);
            acc2[a][2] = fmaf(av, bv.z, acc2[a][2]);
            acc2[a][3] = fmaf(av, bv.w, acc2[a][3]);
        }
    }
    float t3 = 0.f, t4 = 0.f;
    #pragma unroll
    for (int a = 0; a < 4; a++)
        #pragma unroll
        for (int b = 0; b < 4; b++) {
            float e2 = acc2[a][b];
            t3 += e2 * sE[(slab + r0 + a) * EP + j0 + b];
            t4 += e2 * e2;
        }

    __half* Ak = g_Ah + (size_t)k * Dd * Dd;
    float rb[4] = {0.f, 0.f, 0.f, 0.f};
    #pragma unroll
    for (int a = 0; a < 4; a++) {
        int i = slab + r0 + a;
        #pragma unroll
        for (int b = 0; b < 4; b++) {
            int j = j0 + b;
            float e = sE[i * EP + j];
            float v = ((i == j) ? 1.f : 0.f) - 0.5f * e + 0.375f * acc2[a][b];
            Ak[sw_off((uint32_t)i, (uint32_t)j) >> 1] = __float2half(v);
            rb[a] = fmaf(v, sMu[j], rb[a]);
        }
    }
    #pragma unroll
    for (int a = 0; a < 4; a++) {
        #pragma unroll
        for (int o = 16; o > 0; o >>= 1)
            rb[a] += __shfl_xor_sync(0xffffffffu, rb[a], o);
        if (tj == 0) g_b[k * Dd + slab + r0 + a] = rb[a];
    }

    cta_red2(t1, t2, aux);
    if (tid == 0) {
        g_tp1[(k * 4 + blockIdx.y) * 2 + 0] = t1;
        g_tp1[(k * 4 + blockIdx.y) * 2 + 1] = t2;
    }
    __syncthreads();
    cta_red2(t3, t4, aux);
    if (tid == 0) {
        g_tp2[(k * 4 + blockIdx.y) * 2 + 0] = t3;
        g_tp2[(k * 4 + blockIdx.y) * 2 + 1] = t4;
    }
}

// ---------------------------------------------------------------------------
// P3: cst[k] from trace partials.
// ---------------------------------------------------------------------------
__global__ void prep3(const float* __restrict__ w) {
    int k = threadIdx.x;
    if (k >= Kc) return;
    float t1 = 0.f, t2 = 0.f, t3 = 0.f, t4 = 0.f;
    #pragma unroll
    for (int s = 0; s < 4; s++) {
        t1 += g_tp1[(k * 4 + s) * 2 + 0];
        t2 += g_tp1[(k * 4 + s) * 2 + 1];
        t3 += g_tp2[(k * 4 + s) * 2 + 0];
        t4 += g_tp2[(k * 4 + s) * 2 + 1];
    }
    float hld = 0.5f * (t1 - 0.5f * t2 + t3 / 3.f - 0.25f * t4);
    g_cst[k] = -0.5f * (float)Dd * 1.8378770664093453f - hld + logf(w[k]);
}

// ---------------------------------------------------------------------------
// Main: grid (NCTA, KSPL); A staged in pairs; prologue before X convert.
// Epilogue: wn halves combined via smem (double-buffered by s-parity) ->
// ONE combined partial per (k, n) -> halves g_pr traffic.
// ---------------------------------------------------------------------------
#define XS_OFF 0
#define A0_OFF 32768           // pair buffer 0: 64KB
#define A1_OFF 98304           // pair buffer 1: 64KB
#define BS_OFF 163840          // KPC*Dd fp32 = 8KB
#define RD_OFF 172032          // red[2][128] fp32 = 1KB
#define SMEM_MAIN 173056

__device__ __forceinline__ void loadB(uint32_t bbuf[8][2], uint32_t ab, int ks,
                                      int wn, int l) {
    #pragma unroll
    for (int p = 0; p < 4; p++) {
        uint32_t tmp[4];
        int row = wn * 64 + p * 16 + ((l >> 4) << 3) + (l & 7);
        int ch  = ks * 2 + ((l >> 3) & 1);
        ldsm4t(tmp, ab + (uint32_t)(row * 256 + ((ch ^ (row & 7)) << 4)));
        bbuf[p*2][0]   = tmp[0]; bbuf[p*2][1]   = tmp[1];
        bbuf[p*2+1][0] = tmp[2]; bbuf[p*2+1][1] = tmp[3];
    }
}

__global__ void __launch_bounds__(256, 1) gmm_main(const float* __restrict__ x) {
    extern __shared__ char sm[];
    const uint32_t smb = s2u(sm);
    const int tid = threadIdx.x;
    const int wid = tid >> 5, l = tid & 31;
    const int wm = wid & 3, wn = wid >> 2;
    const int n0 = blockIdx.x * 128;
    const int k0 = blockIdx.y * KPC;

    float* bs  = (float*)(sm + BS_OFF);
    float* red = (float*)(sm + RD_OFF);   // [2][128], indexed by s parity

    // Prologue FIRST: pair (k0, k0+1) -> buf0; latency hides behind X convert.
    for (int ch = tid; ch < 4096; ch += 256)
        cpasync16(smb + A0_OFF + ch * 16, (const char*)g_Ah + (size_t)k0 * 32768 + ch * 16);
    CP_COMMIT();

    // X tile -> f16 swizzled SMEM
    for (int ch = tid; ch < 2048; ch += 256) {
        int row = ch >> 4, cc = (ch & 15) * 8;
        const float4* src = (const float4*)(x + (size_t)(n0 + row) * Dd + cc);
        float4 u = src[0], v = src[1];
        __half2 h[4] = { __floats2half2_rn(u.x, u.y), __floats2half2_rn(u.z, u.w),
                         __floats2half2_rn(v.x, v.y), __floats2half2_rn(v.z, v.w) };
        *(uint4*)(sm + XS_OFF + sw_off((uint32_t)row, (uint32_t)cc)) = *(uint4*)h;
    }
    for (int i = tid; i < KPC * Dd; i += 256) bs[i] = g_b[k0 * Dd + i];
    __syncthreads();

    // Preload X fragments: 2 m-tiles x 8 k-steps, register resident.
    uint32_t xa[2][8][4];
    #pragma unroll
    for (int mt = 0; mt < 2; mt++)
        #pragma unroll
        for (int ks = 0; ks < 8; ks++) {
            int row = wm * 32 + mt * 16 + (l & 15);
            int ch  = ks * 2 + (l >> 4);
            ldsm4(xa[mt][ks], smb + XS_OFF + (uint32_t)(row * 256 + ((ch ^ (row & 7)) << 4)));
        }

    for (int kp = 0; kp < KPC; kp += 2) {
        __syncthreads();  // all warps done reading the buffer being overwritten
        {   // prefetch next pair
            int kn = k0 + ((kp + 2) & (KPC - 1));
            const char* src = (const char*)g_Ah + (size_t)kn * 32768;
            uint32_t dst = smb + ((((kp >> 1) + 1) & 1) ? A1_OFF : A0_OFF);
            for (int ch = tid; ch < 4096; ch += 256)
                cpasync16(dst + ch * 16, src + ch * 16);
            CP_COMMIT();
        }
        CP_WAIT1();
        __syncthreads();  // current pair visible

        const uint32_t pb = smb + (((kp >> 1) & 1) ? A1_OFF : A0_OFF);

        #pragma unroll
        for (int s = 0; s < 2; s++) {
            const int kk = kp + s;
            const int k = k0 + kk;
            const uint32_t ab = pb + s * 32768;

            float acc[2][8][4];
            #pragma unroll
            for (int mt = 0; mt < 2; mt++)
                #pragma unroll
                for (int nt = 0; nt < 8; nt++)
                    #pragma unroll
                    for (int e = 0; e < 4; e++) acc[mt][nt][e] = 0.f;

            uint32_t bb[2][8][2];
            loadB(bb[0], ab, 0, wn, l);
            #pragma unroll
            for (int ks = 0; ks < 8; ks++) {
                if (ks < 7) loadB(bb[(ks + 1) & 1], ab, ks + 1, wn, l);
                #pragma unroll
                for (int mt = 0; mt < 2; mt++)
                    #pragma unroll
                    for (int nt = 0; nt < 8; nt++)
                        mma16816(acc[mt][nt], xa[mt][ks], bb[ks & 1][nt]);
            }

            float pr[4] = {0.f, 0.f, 0.f, 0.f};
            #pragma unroll
            for (int nt = 0; nt < 8; nt++) {
                int d0 = wn * 64 + nt * 8 + (l & 3) * 2;
                float b0 = bs[kk * Dd + d0], b1 = bs[kk * Dd + d0 + 1];
                #pragma unroll
                for (int mt = 0; mt < 2; mt++) {
                    float t0 = acc[mt][nt][0] - b0, t1 = acc[mt][nt][1] - b1;
                    pr[mt*2]   = fmaf(t0, t0, fmaf(t1, t1, pr[mt*2]));
                    float t2 = acc[mt][nt][2] - b0, t3 = acc[mt][nt][3] - b1;
                    pr[mt*2+1] = fmaf(t2, t2, fmaf(t3, t3, pr[mt*2+1]));
                }
            }
            #pragma unroll
            for (int q = 0; q < 4; q++) {
                pr[q] += __shfl_xor_sync(0xffffffffu, pr[q], 1);
                pr[q] += __shfl_xor_sync(0xffffffffu, pr[q], 2);
            }

            // combine wn halves via smem (buffer s avoids WAR across the pair)
            float* rd = red + s * 128 + wm * 32;
            const int rq = l >> 2;
            if (wn == 1 && (l & 3) == 0) {
                rd[rq]      = pr[0];
                rd[8 + rq]  = pr[1];
                rd[16 + rq] = pr[2];
                rd[24 + rq] = pr[3];
            }
            __syncthreads();
            if (wn == 0 && (l & 3) == 0) {
                float* pk = g_pr + ((size_t)k * NCTA + blockIdx.x) * 128 + wm * 32;
                pk[rq]      = pr[0] + rd[rq];
                pk[8 + rq]  = pr[1] + rd[8 + rq];
                pk[16 + rq] = pr[2] + rd[16 + rq];
                pk[24 + rq] = pr[3] + rd[24 + rq];
            }
        }
    }
}

// ---------------------------------------------------------------------------
// LSE kernel: 32 independent loads per thread (combined partials), max-tree.
// ---------------------------------------------------------------------------
__global__ __launch_bounds__(256) void lse_kernel(float* __restrict__ out) {
    __shared__ float cs[Kc];
    if (threadIdx.x < Kc) cs[threadIdx.x] = g_cst[threadIdx.x];
    __syncthreads();
    const int n = blockIdx.x * 256 + threadIdx.x;
    const float* p = g_pr + n;     // [k][n] with stride Nn

    float v[Kc];
    #pragma unroll
    for (int k = 0; k < Kc; k++)
        v[k] = p[(size_t)k * Nn];  // independent loads -> front-batched
    #pragma unroll
    for (int k = 0; k < Kc; k++)
        v[k] = cs[k] - 0.5f * v[k];

    float mx = v[0];
    #pragma unroll
    for (int k = 1; k < Kc; k++) mx = fmaxf(mx, v[k]);
    float ss = 0.f;
    #pragma unroll
    for (int k = 0; k < Kc; k++) ss += __expf(v[k] - mx);
    out[n] = mx + __logf(ss);
}

// ---------------------------------------------------------------------------
extern "C" void kernel_launch(void* const* d_in, const int* in_sizes, int n_in,
                              void* d_out, int out_size) {
    const float *x = 0, *mu = 0, *cov = 0, *w = 0;
    for (int i = 0; i < n_in; i++) {
        long s = in_sizes[i];
        const float* p = (const float*)d_in[i];
        if      (s == (long)Nn * Dd)      x   = p;
        else if (s == (long)Kc * Dd * Dd) cov = p;
        else if (s == (long)Kc * Dd)      mu  = p;
        else if (s == (long)Kc)           w   = p;
    }

    const int p12_smem = (Dd * EP + Dd) * (int)sizeof(float);   // ~68KB
    cudaFuncSetAttribute(prep12,   cudaFuncAttributeMaxDynamicSharedMemorySize, p12_smem);
    cudaFuncSetAttribute(gmm_main, cudaFuncAttributeMaxDynamicSharedMemorySize, SMEM_MAIN);

    prep12<<<dim3(Kc, 4), 256, p12_smem>>>(cov, mu);
    prep3<<<1, 32>>>(w);
    gmm_main<<<dim3(NCTA, KSPL), 256, SMEM_MAIN>>>(x);
    lse_kernel<<<Nn / 256, 256>>>((float*)d_out);
}